// round 1
// baseline (speedup 1.0000x reference)
#include <cuda_runtime.h>
#include <cuda_bf16.h>
#include <cstdint>

// Problem constants (fixed shapes)
#define CDIM 2048
#define EXP  64
#define TOPK 6
#define TOKB 128          // tokens per block
#define KC   64           // k-chunk per stage
#define LDK  68           // padded smem row stride (floats), 16B-aligned
#define NST  (CDIM / KC)  // 32 stages
#define NTHR 256
#define BT   16384        // total tokens (4*4096)
#define TDIM 4096
#define BDIM 4

#define XS_FLOATS (TOKB * LDK)   // 8704
#define WS_FLOATS (EXP * LDK)    // 4352
#define SMEM_FLOATS (2 * XS_FLOATS + 2 * WS_FLOATS)  // 26112
#define SMEM_BYTES (SMEM_FLOATS * 4)                 // 104448

__device__ float g_sums[BDIM * EXP];
__device__ float g_cnts[BDIM * EXP];

__device__ __forceinline__ void cp16(void* smem_ptr, const void* gptr) {
    unsigned saddr = (unsigned)__cvta_generic_to_shared(smem_ptr);
    asm volatile("cp.async.cg.shared.global [%0], [%1], 16;\n" :: "r"(saddr), "l"(gptr));
}
__device__ __forceinline__ void cp_commit() {
    asm volatile("cp.async.commit_group;\n" ::: "memory");
}
__device__ __forceinline__ unsigned long long pk(float a, float b) {
    unsigned long long r;
    asm("mov.b64 %0, {%1, %2};" : "=l"(r) : "f"(a), "f"(b));
    return r;
}
__device__ __forceinline__ void ffma2(unsigned long long& d, unsigned long long a, unsigned long long b) {
    asm("fma.rn.f32x2 %0, %1, %2, %0;" : "+l"(d) : "l"(a), "l"(b));
}
__device__ __forceinline__ void unpk(unsigned long long v, float& lo, float& hi) {
    asm("mov.b64 {%0, %1}, %2;" : "=f"(lo), "=f"(hi) : "l"(v));
}

__global__ void __launch_bounds__(NTHR, 1)
gate_kernel(const float* __restrict__ x, const float* __restrict__ w, float* __restrict__ out) {
    extern __shared__ float sm[];
    float* xs0 = sm;
    float* xs1 = sm + XS_FLOATS;
    float* ws0 = sm + 2 * XS_FLOATS;
    float* ws1 = ws0 + WS_FLOATS;
    float* xsb[2] = {xs0, xs1};
    float* wsb[2] = {ws0, ws1};

    __shared__ float s_sums[EXP];
    __shared__ float s_cnt[EXP];

    const int tid = threadIdx.x;
    const int blk = blockIdx.x;
    if (tid < EXP) { s_sums[tid] = 0.f; s_cnt[tid] = 0.f; }

    const float* xblk = x + (size_t)blk * TOKB * CDIM;

    const int tok_g = tid >> 3;   // 0..31, token = tok_g + 32*i
    const int exp_g = tid & 7;    // 0..7,  expert = exp_g + 8*j

    unsigned long long acc[4][8];
#pragma unroll
    for (int i = 0; i < 4; i++)
#pragma unroll
        for (int j = 0; j < 8; j++) acc[i][j] = 0ULL;

    // ---- stage loader ----
    auto load_stage = [&](int s, int buf) {
        float* xd = xsb[buf];
        float* wd = wsb[buf];
#pragma unroll
        for (int j = 0; j < 8; j++) {  // 2048 float4 of x
            int f  = tid + j * NTHR;
            int t  = f >> 4;
            int k4 = f & 15;
            cp16(xd + t * LDK + k4 * 4, xblk + (size_t)t * CDIM + s * KC + k4 * 4);
        }
#pragma unroll
        for (int j = 0; j < 4; j++) {  // 1024 float4 of w
            int f  = tid + j * NTHR;
            int e  = f >> 4;
            int k4 = f & 15;
            cp16(wd + e * LDK + k4 * 4, w + (size_t)e * CDIM + s * KC + k4 * 4);
        }
        cp_commit();
    };

    load_stage(0, 0);
    load_stage(1, 1);

    for (int s = 0; s < NST; s++) {
        if (s + 1 < NST) {
            asm volatile("cp.async.wait_group 1;\n" ::: "memory");
        } else {
            asm volatile("cp.async.wait_group 0;\n" ::: "memory");
        }
        __syncthreads();

        const float* xp = xsb[s & 1];
        const float* wp = wsb[s & 1];

#pragma unroll 2
        for (int k0 = 0; k0 < KC; k0 += 4) {
            unsigned long long xa[4], xb2[4], wa[8], wb[8];
#pragma unroll
            for (int i = 0; i < 4; i++) {
                float4 v = *reinterpret_cast<const float4*>(xp + (tok_g + 32 * i) * LDK + k0);
                xa[i]  = pk(v.x, v.y);
                xb2[i] = pk(v.z, v.w);
            }
#pragma unroll
            for (int j = 0; j < 8; j++) {
                float4 v = *reinterpret_cast<const float4*>(wp + (exp_g + 8 * j) * LDK + k0);
                wa[j] = pk(v.x, v.y);
                wb[j] = pk(v.z, v.w);
            }
#pragma unroll
            for (int i = 0; i < 4; i++)
#pragma unroll
                for (int j = 0; j < 8; j++) {
                    ffma2(acc[i][j], xa[i], wa[j]);
                    ffma2(acc[i][j], xb2[i], wb[j]);
                }
        }
        __syncthreads();
        if (s + 2 < NST) load_stage(s + 2, s & 1);
    }

    // ---- logits -> smem (rows padded to 65 floats, conflict-free per-thread scan) ----
    float* lsm = sm;  // 128*65 = 8320 floats, fits in xs0 region (8704)
#pragma unroll
    for (int i = 0; i < 4; i++)
#pragma unroll
        for (int j = 0; j < 8; j++) {
            float lo, hi;
            unpk(acc[i][j], lo, hi);
            lsm[(tok_g + 32 * i) * 65 + (exp_g + 8 * j)] = lo + hi;
        }
    __syncthreads();

    if (tid < TOKB) {
        float* row = lsm + tid * 65;

        // register top-6 (descending; strict > => lax.top_k tie-break: earlier index wins)
        float v0 = -1e38f, v1 = -1e38f, v2 = -1e38f, v3 = -1e38f, v4 = -1e38f, v5 = -1e38f;
        int   i0 = 0, i1 = 0, i2 = 0, i3 = 0, i4 = 0, i5 = 0;
        for (int e = 0; e < EXP; e++) {
            float l = row[e];
            if (l > v5) {
                v5 = l; i5 = e;
                if (v5 > v4) { float tf = v4; v4 = v5; v5 = tf; int ti = i4; i4 = i5; i5 = ti; }
                if (v4 > v3) { float tf = v3; v3 = v4; v4 = tf; int ti = i3; i3 = i4; i4 = ti; }
                if (v3 > v2) { float tf = v2; v2 = v3; v3 = tf; int ti = i2; i2 = i3; i3 = ti; }
                if (v2 > v1) { float tf = v1; v1 = v2; v2 = tf; int ti = i1; i1 = i2; i2 = ti; }
                if (v1 > v0) { float tf = v0; v0 = v1; v1 = tf; int ti = i0; i0 = i1; i1 = ti; }
            }
        }

        // softmax (select done on logits; exp only for weights/aux)
        float m = v0;
        float ssum = 0.f;
        for (int e = 0; e < EXP; e++) {
            float p = expf(row[e] - m);
            ssum += p;
            row[e] = p;
        }
        float inv = 1.0f / ssum;

        const size_t tg = (size_t)blk * TOKB + tid;
        float* out_idx = out;
        float* out_wgt = out + (size_t)BT * TOPK;

        out_idx[tg * TOPK + 0] = (float)i0;
        out_idx[tg * TOPK + 1] = (float)i1;
        out_idx[tg * TOPK + 2] = (float)i2;
        out_idx[tg * TOPK + 3] = (float)i3;
        out_idx[tg * TOPK + 4] = (float)i4;
        out_idx[tg * TOPK + 5] = (float)i5;

        out_wgt[tg * TOPK + 0] = row[i0] * inv;
        out_wgt[tg * TOPK + 1] = row[i1] * inv;
        out_wgt[tg * TOPK + 2] = row[i2] * inv;
        out_wgt[tg * TOPK + 3] = row[i3] * inv;
        out_wgt[tg * TOPK + 4] = row[i4] * inv;
        out_wgt[tg * TOPK + 5] = row[i5] * inv;

        // aux-loss partials: per-expert prob sums (staggered to spread banks) + top-k counts
        for (int jj = 0; jj < EXP; jj++) {
            int e = (tid + jj) & (EXP - 1);
            atomicAdd(&s_sums[e], row[e] * inv);
        }
        atomicAdd(&s_cnt[i0], 1.0f);
        atomicAdd(&s_cnt[i1], 1.0f);
        atomicAdd(&s_cnt[i2], 1.0f);
        atomicAdd(&s_cnt[i3], 1.0f);
        atomicAdd(&s_cnt[i4], 1.0f);
        atomicAdd(&s_cnt[i5], 1.0f);
    }
    __syncthreads();

    if (tid < EXP) {
        int b = blk >> 5;  // 32 blocks (4096 tokens) per batch element
        atomicAdd(&g_sums[b * EXP + tid], s_sums[tid]);
        atomicAdd(&g_cnts[b * EXP + tid], s_cnt[tid]);
    }
}

__global__ void zero_kernel() {
    int t = threadIdx.x;
    if (t < BDIM * EXP) { g_sums[t] = 0.f; g_cnts[t] = 0.f; }
}

__global__ void aux_kernel(float* __restrict__ out) {
    __shared__ float red[256];
    int t = threadIdx.x;
    red[t] = g_cnts[t] * g_sums[t];
    __syncthreads();
#pragma unroll
    for (int s = 128; s > 0; s >>= 1) {
        if (t < s) red[t] += red[t + s];
        __syncthreads();
    }
    if (t == 0) {
        // aux = alpha * (1/B) * sum_{b,e} (cnt*E/(T*K)) * (sums/T)
        const float scale = (float)(0.001 * 64.0 / ((double)4 * 4096.0 * 6.0 * 4096.0));
        out[(size_t)BT * 12] = red[0] * scale;
    }
}

extern "C" void kernel_launch(void* const* d_in, const int* in_sizes, int n_in,
                              void* d_out, int out_size) {
    const float* x = (const float*)d_in[0];
    const float* w = (const float*)d_in[1];
    float* out = (float*)d_out;

    cudaFuncSetAttribute(gate_kernel, cudaFuncAttributeMaxDynamicSharedMemorySize, SMEM_BYTES);

    zero_kernel<<<1, 256>>>();
    gate_kernel<<<BT / TOKB, NTHR, SMEM_BYTES>>>(x, w, out);
    aux_kernel<<<1, 256>>>(out);
}

// round 5
// speedup vs baseline: 1.0458x; 1.0458x over previous
#include <cuda_runtime.h>
#include <cuda_bf16.h>
#include <cstdint>

#define NTHR 256
#define TOKB 128
#define EXPN 64
#define CDIM 2048
#define BT   16384
#define BDIM 4
#define TOPK 6
#define NKS  128                 // k-steps of 16
#define CH   4                   // k-steps per chunk
#define KSTEP_U32 1024           // u32 per k-step packed W (4 jp * 2 grp * 32 lanes * 4)
#define CHUNK_U32 (CH*KSTEP_U32) // 4096 u32 = 16 KB
#define LSTR 66
#define TAU  1.0e-4f
#define SMEM_BYTES (4*CHUNK_U32*4 + TOKB*LSTR*4)   // 65536 + 33792

__device__ float g_sums[BDIM * EXPN];
__device__ float g_cnts[BDIM * EXPN];
__device__ int   g_flagcnt;
__device__ int   g_flags[BT];
__device__ uint32_t wsg[NKS * KSTEP_U32];   // 512 KB packed 2-plane W fragments

static __device__ __forceinline__ void cp16(void* smem_ptr, const void* gptr) {
    unsigned saddr = (unsigned)__cvta_generic_to_shared(smem_ptr);
    asm volatile("cp.async.cg.shared.global [%0], [%1], 16;\n" :: "r"(saddr), "l"(gptr));
}
#define CP_COMMIT() asm volatile("cp.async.commit_group;\n" ::: "memory")

static __device__ __forceinline__ void mma16816(float* c, const uint32_t* a,
                                                uint32_t b0, uint32_t b1) {
    asm volatile("mma.sync.aligned.m16n8k16.row.col.f32.bf16.bf16.f32 "
        "{%0,%1,%2,%3}, {%4,%5,%6,%7}, {%8,%9}, {%0,%1,%2,%3};"
        : "+f"(c[0]), "+f"(c[1]), "+f"(c[2]), "+f"(c[3])
        : "r"(a[0]), "r"(a[1]), "r"(a[2]), "r"(a[3]), "r"(b0), "r"(b1));
}

// exact 2-way bf16 split of a float pair -> two bf16x2 words (lo=f0, hi=f1)
static __device__ __forceinline__ void split2(float f0, float f1,
                                              uint32_t& o0, uint32_t& o1) {
    __nv_bfloat162 b = __floats2bfloat162_rn(f0, f1);
    uint32_t u = *(uint32_t*)&b;
    o0 = u;
    float g0 = __int_as_float(u << 16);
    float g1 = __int_as_float(u & 0xffff0000u);
    __nv_bfloat162 c = __floats2bfloat162_rn(f0 - g0, f1 - g1);
    o1 = *(uint32_t*)&c;
}

// ---------------- W prep: 2-plane split, packed in B-fragment lane order ----------------
__global__ void prep_kernel(const float* __restrict__ w) {
    int id = blockIdx.x * 256 + threadIdx.x;   // 32768 = 128 ksteps * 8 ntiles * 32 lanes
    if (id < BDIM * EXPN) { g_sums[id] = 0.f; g_cnts[id] = 0.f; }
    if (id == 0) g_flagcnt = 0;
    int s = id >> 8;
    int j = (id >> 5) & 7;
    int l = id & 31;
    int n  = 8 * j + (l >> 2);
    int k0 = s * 16 + (l & 3) * 2;
    const float* wr = w + (size_t)n * CDIM + k0;
    float2 flo = *(const float2*)wr;        // b0 pair (k0, k0+1)
    float2 fhi = *(const float2*)(wr + 8);  // b1 pair (k0+8, k0+9)
    uint32_t A, B, C, D;
    split2(flo.x, flo.y, A, B);
    split2(fhi.x, fhi.y, C, D);
    uint32_t base = (uint32_t)(((s * 4 + (j >> 1)) * 2 + (j & 1)) * 128 + l * 4);
    *(uint4*)&wsg[base] = make_uint4(A, C, B, D);
}

// ---------------- main gate kernel ----------------
__global__ void __launch_bounds__(NTHR, 1)
gate_kernel(const float* __restrict__ x, float* __restrict__ out) {
    extern __shared__ char smem[];
    uint32_t* wbuf = (uint32_t*)smem;                 // 4 x 16KB chunk buffers
    float* lsm = (float*)(smem + 4 * CHUNK_U32 * 4);  // 128 x 66 logits
    __shared__ float s_sums[EXPN];
    __shared__ float s_cnt[EXPN];

    const int tid  = threadIdx.x;
    const int wid  = tid >> 5;
    const int lane = tid & 31;
    const int blk  = blockIdx.x;
    const int wg   = wid & 3;    // token group (32 tokens)
    const int kh   = wid >> 2;   // k-half

    if (tid < EXPN) { s_sums[tid] = 0.f; s_cnt[tid] = 0.f; }

    const int r  = lane >> 2;
    const int c0 = (lane & 3) * 2;
    const float* xr0 = x + ((size_t)blk * TOKB + wg * 32 + r) * CDIM + kh * 1024;
    const float* xr1 = xr0 + (size_t)16 * CDIM;

    float cacc[2][8][4];
#pragma unroll
    for (int m = 0; m < 2; m++)
#pragma unroll
        for (int j = 0; j < 8; j++)
#pragma unroll
            for (int q = 0; q < 4; q++) cacc[m][j][q] = 0.f;

    auto load2 = [&](int c) {
        int par = c & 1;
        const uint4* s0 = (const uint4*)(wsg + (size_t)c * CHUNK_U32);
        const uint4* s1 = (const uint4*)(wsg + (size_t)(16 + c) * CHUNK_U32);
        uint4* d0 = (uint4*)(wbuf + par * CHUNK_U32);
        uint4* d1 = (uint4*)(wbuf + (2 + par) * CHUNK_U32);
#pragma unroll
        for (int i = 0; i < 4; i++) cp16(d0 + tid + i * NTHR, s0 + tid + i * NTHR);
#pragma unroll
        for (int i = 0; i < 4; i++) cp16(d1 + tid + i * NTHR, s1 + tid + i * NTHR);
        CP_COMMIT();
    };

    load2(0);
    load2(1);

    for (int c = 0; c < 16; c++) {
        if (c + 1 < 16) asm volatile("cp.async.wait_group 1;\n" ::: "memory");
        else            asm volatile("cp.async.wait_group 0;\n" ::: "memory");
        __syncthreads();

        const uint32_t* wb = wbuf + (kh * 2 + (c & 1)) * CHUNK_U32;

#pragma unroll
        for (int kc = 0; kc < CH; kc++) {
            const int koff = (c * 4 + kc) * 16 + c0;
            uint32_t A0[2][4], A1[2][4];
#pragma unroll
            for (int m = 0; m < 2; m++) {
                const float* xp = (m == 0 ? xr0 : xr1) + koff;
                float2 l0 = *(const float2*)xp;
                float2 l1 = *(const float2*)(xp + 8 * CDIM);
                float2 h0 = *(const float2*)(xp + 8);
                float2 h1 = *(const float2*)(xp + 8 * CDIM + 8);
                split2(l0.x, l0.y, A0[m][0], A1[m][0]);
                split2(l1.x, l1.y, A0[m][1], A1[m][1]);
                split2(h0.x, h0.y, A0[m][2], A1[m][2]);
                split2(h1.x, h1.y, A0[m][3], A1[m][3]);
            }
            const uint4* wk = (const uint4*)(wb + kc * KSTEP_U32) + lane;
#pragma unroll
            for (int jp = 0; jp < 4; jp++) {
                uint4 G0 = wk[jp * 64];
                uint4 G1 = wk[jp * 64 + 32];
#pragma unroll
                for (int m = 0; m < 2; m++) {
                    float* ce = cacc[m][2 * jp];
                    float* co = cacc[m][2 * jp + 1];
                    mma16816(ce, A0[m], G0.x, G0.y);
                    mma16816(ce, A0[m], G0.z, G0.w);
                    mma16816(ce, A1[m], G0.x, G0.y);
                    mma16816(co, A0[m], G1.x, G1.y);
                    mma16816(co, A0[m], G1.z, G1.w);
                    mma16816(co, A1[m], G1.x, G1.y);
                }
            }
        }
        __syncthreads();
        if (c + 2 < 16) load2(c + 2);
    }

    // ---- combine k-halves ----
    if (kh == 0) {
#pragma unroll
        for (int m = 0; m < 2; m++)
#pragma unroll
            for (int j = 0; j < 8; j++) {
                int row = wg * 32 + m * 16 + r;
                int nb = 8 * j + c0;
                *(float2*)&lsm[row * LSTR + nb]       = make_float2(cacc[m][j][0], cacc[m][j][1]);
                *(float2*)&lsm[(row + 8) * LSTR + nb] = make_float2(cacc[m][j][2], cacc[m][j][3]);
            }
    }
    __syncthreads();
    if (kh == 1) {
#pragma unroll
        for (int m = 0; m < 2; m++)
#pragma unroll
            for (int j = 0; j < 8; j++) {
                int row = wg * 32 + m * 16 + r;
                int nb = 8 * j + c0;
                float2 a = *(float2*)&lsm[row * LSTR + nb];
                float2 b = *(float2*)&lsm[(row + 8) * LSTR + nb];
                *(float2*)&lsm[row * LSTR + nb]       = make_float2(a.x + cacc[m][j][0], a.y + cacc[m][j][1]);
                *(float2*)&lsm[(row + 8) * LSTR + nb] = make_float2(b.x + cacc[m][j][2], b.y + cacc[m][j][3]);
            }
    }
    __syncthreads();

    // ---- per-token epilogue: top-7 tracking + flagging ----
    if (tid < TOKB) {
        float* row = lsm + tid * LSTR;

        float v0 = -1e38f, v1 = -1e38f, v2 = -1e38f, v3 = -1e38f, v4 = -1e38f, v5 = -1e38f, v6 = -1e38f;
        int   i0 = 0, i1 = 0, i2 = 0, i3 = 0, i4 = 0, i5 = 0;
        for (int e = 0; e < EXPN; e++) {
            float l = row[e];
            if (l > v6) {
                v6 = l;
                int ie = e;
                if (v6 > v5) { float t = v5; v5 = v6; v6 = t; int u = i5; i5 = ie; ie = u;
                if (v5 > v4) { t = v4; v4 = v5; v5 = t; u = i4; i4 = i5; i5 = u;
                if (v4 > v3) { t = v3; v3 = v4; v4 = t; u = i3; i3 = i4; i4 = u;
                if (v3 > v2) { t = v2; v2 = v3; v3 = t; u = i2; i2 = i3; i3 = u;
                if (v2 > v1) { t = v1; v1 = v2; v2 = t; u = i1; i1 = i2; i2 = u;
                if (v1 > v0) { t = v0; v0 = v1; v1 = t; u = i0; i0 = i1; i1 = u; } } } } } }
            }
        }

        float mg = v0 - v1;
        mg = fminf(mg, v1 - v2);
        mg = fminf(mg, v2 - v3);
        mg = fminf(mg, v3 - v4);
        mg = fminf(mg, v4 - v5);
        mg = fminf(mg, v5 - v6);
        const int tok = blk * TOKB + tid;
        if (mg < TAU) {
            int slot = atomicAdd(&g_flagcnt, 1);
            g_flags[slot] = tok;
        }

        float m = v0;
        float ssum = 0.f;
        for (int e = 0; e < EXPN; e++) {
            float p = expf(row[e] - m);
            ssum += p;
            row[e] = p;
        }
        float inv = 1.0f / ssum;

        const size_t g = (size_t)tok;
        float* out_idx = out;
        float* out_wgt = out + (size_t)BT * TOPK;

        out_idx[g * TOPK + 0] = (float)i0;
        out_idx[g * TOPK + 1] = (float)i1;
        out_idx[g * TOPK + 2] = (float)i2;
        out_idx[g * TOPK + 3] = (float)i3;
        out_idx[g * TOPK + 4] = (float)i4;
        out_idx[g * TOPK + 5] = (float)i5;

        out_wgt[g * TOPK + 0] = row[i0] * inv;
        out_wgt[g * TOPK + 1] = row[i1] * inv;
        out_wgt[g * TOPK + 2] = row[i2] * inv;
        out_wgt[g * TOPK + 3] = row[i3] * inv;
        out_wgt[g * TOPK + 4] = row[i4] * inv;
        out_wgt[g * TOPK + 5] = row[i5] * inv;

        for (int jj = 0; jj < EXPN; jj++) {
            int e = (tid + jj) & (EXPN - 1);
            atomicAdd(&s_sums[e], row[e] * inv);
        }
        atomicAdd(&s_cnt[i0], 1.0f);
        atomicAdd(&s_cnt[i1], 1.0f);
        atomicAdd(&s_cnt[i2], 1.0f);
        atomicAdd(&s_cnt[i3], 1.0f);
        atomicAdd(&s_cnt[i4], 1.0f);
        atomicAdd(&s_cnt[i5], 1.0f);
    }
    __syncthreads();

    if (tid < EXPN) {
        int b = blk >> 5;
        atomicAdd(&g_sums[b * EXPN + tid], s_sums[tid]);
        atomicAdd(&g_cnts[b * EXPN + tid], s_cnt[tid]);
    }
}

// ---------------- fixup: bit-exact replication of the R1 fp32 summation order ----------------
// logit = (sum over even k ascending, fmaf chain) + (sum over odd k ascending, fmaf chain)
__global__ void __launch_bounds__(256, 1)
fixup_kernel(const float* __restrict__ x, const float* __restrict__ w,
             float* __restrict__ out) {
    __shared__ float ws[EXPN * 129];   // w k-chunk, stride 129 (conflict-free)
    __shared__ float lg[4][EXPN];
    const int tid = threadIdx.x;
    const int tg  = tid >> 6;   // token slot 0..3
    const int e   = tid & 63;   // expert
    const int nflag = g_flagcnt;

    for (int base = blockIdx.x * 4; base < nflag; base += gridDim.x * 4) {
        const int fi  = base + tg;
        const int tok = g_flags[fi < nflag ? fi : (nflag - 1)];

        float accE = 0.f, accO = 0.f;
        for (int ch = 0; ch < 16; ch++) {
            __syncthreads();
            // stage w[:, ch*128 : ch*128+128] -> ws (coalesced)
            for (int i = tid; i < EXPN * 32; i += 256) {
                int row = i >> 5;
                int c4  = i & 31;
                float4 v = *(const float4*)(w + (size_t)row * CDIM + ch * 128 + c4 * 4);
                float* d = &ws[row * 129 + c4 * 4];
                d[0] = v.x; d[1] = v.y; d[2] = v.z; d[3] = v.w;
            }
            __syncthreads();
            const float* xp = x + (size_t)tok * CDIM + ch * 128;
            const float* wr = &ws[e * 129];
#pragma unroll 8
            for (int kk = 0; kk < 128; kk += 2) {
                float2 xv = *(const float2*)(xp + kk);
                accE = fmaf(xv.x, wr[kk],     accE);
                accO = fmaf(xv.y, wr[kk + 1], accO);
            }
        }
        lg[tg][e] = accE + accO;
        __syncthreads();

        if (tid < 4 && base + tid < nflag) {
            const int t2 = g_flags[base + tid];
            const float* row = lg[tid];
            float v0 = -1e38f, v1 = -1e38f, v2 = -1e38f, v3 = -1e38f, v4 = -1e38f, v5 = -1e38f;
            int   i0 = 0, i1 = 0, i2 = 0, i3 = 0, i4 = 0, i5 = 0;
            for (int k = 0; k < EXPN; k++) {
                float l = row[k];
                if (l > v5) {
                    v5 = l; i5 = k;
                    if (v5 > v4) { float t = v4; v4 = v5; v5 = t; int u = i4; i4 = i5; i5 = u; }
                    if (v4 > v3) { float t = v3; v3 = v4; v4 = t; int u = i3; i3 = i4; i4 = u; }
                    if (v3 > v2) { float t = v2; v2 = v3; v3 = t; int u = i2; i2 = i3; i3 = u; }
                    if (v2 > v1) { float t = v1; v1 = v2; v2 = t; int u = i1; i1 = i2; i2 = u; }
                    if (v1 > v0) { float t = v0; v0 = v1; v1 = t; int u = i0; i0 = i1; i1 = u; }
                }
            }
            float m = v0;
            float ssum = 0.f;
            for (int k = 0; k < EXPN; k++) ssum += expf(row[k] - m);
            float inv = 1.0f / ssum;

            float* out_idx = out;
            float* out_wgt = out + (size_t)BT * TOPK;
            const size_t g = (size_t)t2;
            out_idx[g * TOPK + 0] = (float)i0;
            out_idx[g * TOPK + 1] = (float)i1;
            out_idx[g * TOPK + 2] = (float)i2;
            out_idx[g * TOPK + 3] = (float)i3;
            out_idx[g * TOPK + 4] = (float)i4;
            out_idx[g * TOPK + 5] = (float)i5;
            out_wgt[g * TOPK + 0] = expf(v0 - m) * inv;
            out_wgt[g * TOPK + 1] = expf(v1 - m) * inv;
            out_wgt[g * TOPK + 2] = expf(v2 - m) * inv;
            out_wgt[g * TOPK + 3] = expf(v3 - m) * inv;
            out_wgt[g * TOPK + 4] = expf(v4 - m) * inv;
            out_wgt[g * TOPK + 5] = expf(v5 - m) * inv;
        }
        __syncthreads();
    }
}

__global__ void aux_kernel(float* __restrict__ out) {
    __shared__ float red[256];
    int t = threadIdx.x;
    red[t] = g_cnts[t] * g_sums[t];
    __syncthreads();
#pragma unroll
    for (int s = 128; s > 0; s >>= 1) {
        if (t < s) red[t] += red[t + s];
        __syncthreads();
    }
    if (t == 0) {
        const float scale = (float)(0.001 * 64.0 / ((double)4 * 4096.0 * 6.0 * 4096.0));
        out[(size_t)BT * 12] = red[0] * scale;
    }
}

extern "C" void kernel_launch(void* const* d_in, const int* in_sizes, int n_in,
                              void* d_out, int out_size) {
    const float* x = (const float*)d_in[0];
    const float* w = (const float*)d_in[1];
    float* out = (float*)d_out;

    cudaFuncSetAttribute(gate_kernel, cudaFuncAttributeMaxDynamicSharedMemorySize, SMEM_BYTES);

    prep_kernel<<<128, 256>>>(w);
    gate_kernel<<<BT / TOKB, NTHR, SMEM_BYTES>>>(x, out);
    fixup_kernel<<<64, 256>>>(x, w, out);
    aux_kernel<<<1, 256>>>(out);
}